// round 3
// baseline (speedup 1.0000x reference)
#include <cuda_runtime.h>

// YOLO v1 loss: S=7, NB=2, C=20. predictions [N, 7*7*30], targets [N,7,7,25].
// Output: scalar fp32 loss.
// One thread per grid cell (N*49 = 802816 cells). HBM-bound streaming reduction.

#define S_ 7
#define C_ 20
#define CELL_PRED 30   // C + NB*5
#define CELL_TGT  25   // C + 5
#define LAMBDA_COORD 5.0f
#define LAMBDA_NOOBJ 0.5f
#define EPS_ 1e-6f

__global__ void yolo_zero_out(float* out) { out[0] = 0.0f; }

__device__ __forceinline__ float iou_mid(const float* a, const float* b) {
    float ax1 = a[0] - a[2] * 0.5f, ay1 = a[1] - a[3] * 0.5f;
    float ax2 = a[0] + a[2] * 0.5f, ay2 = a[1] + a[3] * 0.5f;
    float bx1 = b[0] - b[2] * 0.5f, by1 = b[1] - b[3] * 0.5f;
    float bx2 = b[0] + b[2] * 0.5f, by2 = b[1] + b[3] * 0.5f;
    float iw = fmaxf(fminf(ax2, bx2) - fmaxf(ax1, bx1), 0.0f);
    float ih = fmaxf(fminf(ay2, by2) - fmaxf(ay1, by1), 0.0f);
    float inter  = iw * ih;
    float area_a = fabsf((ax2 - ax1) * (ay2 - ay1));
    float area_b = fabsf((bx2 - bx1) * (by2 - by1));
    return inter / (area_a + area_b - inter + EPS_);
}

__global__ __launch_bounds__(256) void yolo_loss_kernel(
    const float* __restrict__ pred,
    const float* __restrict__ tgt,
    float* __restrict__ out,
    int total_cells,
    float invN)
{
    int idx = blockIdx.x * blockDim.x + threadIdx.x;

    float v = 0.0f;
    if (idx < total_cells) {
        const float* p = pred + (size_t)idx * CELL_PRED;
        const float* t = tgt  + (size_t)idx * CELL_TGT;

        // predictions: 30 floats, cell base is 120B -> 8-byte aligned: float2 loads
        float pr[CELL_PRED];
        const float2* p2 = reinterpret_cast<const float2*>(p);
        #pragma unroll
        for (int i = 0; i < CELL_PRED / 2; i++) {
            float2 x = __ldg(p2 + i);
            pr[2 * i]     = x.x;
            pr[2 * i + 1] = x.y;
        }

        // targets: 25 floats, cell base 100B -> only 4-byte aligned: scalar loads
        float tg[CELL_TGT];
        #pragma unroll
        for (int i = 0; i < CELL_TGT; i++) tg[i] = __ldg(t + i);

        // class loss: sum over 20 classes of squared diff
        float cls = 0.0f;
        #pragma unroll
        for (int c = 0; c < C_; c++) {
            float d = pr[c] - tg[c];
            cls = fmaf(d, d, cls);
        }

        bool obj = (tg[C_] == 1.0f);

        // b1 = pr[20..24], b2 = pr[25..29], tbox = tg[20..24]
        float i1 = iou_mid(pr + C_,     tg + C_);
        float i2 = iou_mid(pr + C_ + 5, tg + C_);
        const float* r = (i1 > i2) ? (pr + C_) : (pr + C_ + 5);

        float dx = r[0] - tg[C_ + 0];
        float dy = r[1] - tg[C_ + 1];
        float xy = fmaf(dx, dx, dy * dy);
        float dw = sqrtf(r[2]) - sqrtf(tg[C_ + 2]);
        float dh = sqrtf(r[3]) - sqrtf(tg[C_ + 3]);
        float wh = fmaf(dw, dw, dh * dh);
        float coord = LAMBDA_COORD * (xy + wh);
        float dc = r[4] - tg[C_ + 4];
        float conf = dc * dc;

        float c1 = pr[C_ + 4];      // b1[4]
        float c2 = pr[C_ + 9];      // b2[4]
        float noobj = LAMBDA_NOOBJ * fmaf(c1, c1, c2 * c2);

        v = obj ? (coord + conf + cls) : noobj;
        v *= invN;
    }

    // warp reduce
    #pragma unroll
    for (int off = 16; off > 0; off >>= 1)
        v += __shfl_down_sync(0xFFFFFFFFu, v, off);

    __shared__ float warp_sums[8];
    int lane = threadIdx.x & 31;
    int wid  = threadIdx.x >> 5;
    if (lane == 0) warp_sums[wid] = v;
    __syncthreads();

    if (wid == 0) {
        float s = (lane < (blockDim.x >> 5)) ? warp_sums[lane] : 0.0f;
        #pragma unroll
        for (int off = 4; off > 0; off >>= 1)
            s += __shfl_down_sync(0xFFFFFFFFu, s, off);
        if (lane == 0) atomicAdd(out, s);
    }
}

extern "C" void kernel_launch(void* const* d_in, const int* in_sizes, int n_in,
                              void* d_out, int out_size)
{
    const float* pred = (const float*)d_in[0];
    const float* tgt  = (const float*)d_in[1];
    float* out = (float*)d_out;

    // N from predictions element count: N * S*S*(C+NB*5) = N * 1470
    int N = in_sizes[0] / (S_ * S_ * (C_ + 10));
    int total_cells = N * S_ * S_;
    float invN = 1.0f / (float)N;

    yolo_zero_out<<<1, 1>>>(out);

    int threads = 256;
    int blocks = (total_cells + threads - 1) / threads;
    yolo_loss_kernel<<<blocks, threads>>>(pred, tgt, out, total_cells, invN);
}